// round 10
// baseline (speedup 1.0000x reference)
#include <cuda_runtime.h>
#include <cuda_fp16.h>
#include <math.h>
#include <stdint.h>

#define NN 100000
#define NE 800000
#define NG 64
#define NT 4
#define D 150
#define HIDN 512
#define PASSES 5
#define NC1 1050
#define MLD 1056
#define GILD 456
#define XLD 152
#define NB1 9
#define NB2 4
#define NBM 782
#define FBLK2 20480                // u32 per B col block: 10ks x 16nt x 32lane x 4 (hi0,hi1,mid0,mid1)
#define ABLK (10 * 8 * 128)        // u32 per A row block per array

__device__ float g_h[(size_t)NN * D];
__device__ float g_out1[(size_t)NN * MLD];
__device__ float g_gi[(size_t)NN * GILD];
__device__ float g_biasinc[(size_t)NN * D];
__device__ uint32_t g_Ah[(size_t)NBM * ABLK];
__device__ uint32_t g_Am[(size_t)NBM * ABLK];
__device__ uint32_t g_Ih[(size_t)NBM * ABLK];
__device__ uint32_t g_Im[(size_t)NBM * ABLK];
__device__ uint32_t g_F1i[NB1 * FBLK2];
__device__ uint32_t g_F2i[NB2 * FBLK2];
__device__ float g_bias1[NC1];
__device__ int   g_degt[NN * NT];
__device__ int   g_rowptr[NN + 1];
__device__ int   g_cursor[NN];
__device__ int   g_bsum[128];
__device__ int   g_ebase[NE];
__device__ int   g_gstart[NG + 1];
__device__ float g_x[NG * XLD];

__device__ __forceinline__ uint32_t packh(float x0, float x1) {
    __half2 h = __floats2half2_rn(x0, x1);
    return *reinterpret_cast<uint32_t*>(&h);
}
__device__ __forceinline__ uint32_t split2(float x0, float x1, uint32_t* mid) {
    __half h0 = __float2half_rn(x0), h1 = __float2half_rn(x1);
    float m0 = x0 - __half2float(h0), m1 = x1 - __half2float(h1);
    *mid = packh(m0, m1);
    __half2 hh = __halves2half2(h0, h1);
    return *reinterpret_cast<uint32_t*>(&hh);
}
__device__ __forceinline__ void mma_f16(float* d, const uint32_t* a, const uint32_t* b) {
    asm volatile(
        "mma.sync.aligned.m16n8k16.row.col.f32.f16.f16.f32 "
        "{%0,%1,%2,%3}, {%4,%5,%6,%7}, {%8,%9}, {%0,%1,%2,%3};"
        : "+f"(d[0]), "+f"(d[1]), "+f"(d[2]), "+f"(d[3])
        : "r"(a[0]), "r"(a[1]), "r"(a[2]), "r"(a[3]), "r"(b[0]), "r"(b[1]));
}
__device__ __forceinline__ uint32_t smem_u32(const void* p) {
    uint32_t a;
    asm("{ .reg .u64 t; cvta.to.shared.u64 t, %1; cvt.u32.u64 %0, t; }" : "=r"(a) : "l"(p));
    return a;
}
#define CP_ASYNC16(dst, src) \
    asm volatile("cp.async.cg.shared.global [%0], [%1], 16;" :: "r"(dst), "l"(src) : "memory")
#define CP_COMMIT() asm volatile("cp.async.commit_group;" ::: "memory")
#define CP_WAIT1()  asm volatile("cp.async.wait_group 1;" ::: "memory")

// A fragment addressing (producer side)
__device__ __forceinline__ size_t frag_hidx(int node, int i) {
    int rb = node >> 7, mt = (node >> 4) & 7, r = node & 15;
    int ks = i >> 4, kk = i & 15, w = kk >> 1;
    int lane = (r & 7) * 4 + (w & 3);
    int reg = (r >> 3) + 2 * (w >> 2);
    size_t u32i = (((size_t)rb * 10 + ks) * 8 + mt) * 128 + lane * 4 + reg;
    return u32i * 2 + (i & 1);
}
__device__ __forceinline__ void frag_write(uint32_t* Fh, uint32_t* Fm, int node, int i, float v) {
    __half hi = __float2half_rn(v);
    __half mid = __float2half_rn(v - __half2float(hi));
    size_t fi = frag_hidx(node, i);
    ((__half*)Fh)[fi] = hi;
    ((__half*)Fm)[fi] = mid;
}

// ---------- setup: zero degt, interleaved fragment weights, bias1 ----------
__global__ void setup_weights(const float* __restrict__ We, const float* __restrict__ whh,
                              const float* __restrict__ wih, const float* __restrict__ bhh,
                              uint32_t* __restrict__ F1i, uint32_t* __restrict__ F2i,
                              float* __restrict__ bias1, int* __restrict__ degt) {
    int idx = blockIdx.x * blockDim.x + threadIdx.x;
    if (idx < NN * NT) { degt[idx] = 0; return; }
    idx -= NN * NT;
    if (idx < (NB1 + NB2) * FBLK2) {
        int two = (idx >= NB1 * FBLK2);
        int li = two ? idx - NB1 * FBLK2 : idx;
        int blk = li / FBLK2, r = li % FBLK2;
        int ks = r >> 11, r2 = r & 2047;
        int nt = r2 >> 7, r3 = r2 & 127;
        int lane = r3 >> 2, q = r3 & 3;
        int reg = q & 1;
        int hi_part = (q < 2);
        int n = blk * 128 + nt * 8 + (lane >> 2);
        int w = ks * 8 + reg * 4 + (lane & 3);
        int c0 = 2 * w, c1 = c0 + 1;
        float w0 = 0.f, w1 = 0.f;
        if (!two) {
            if (n < 600) {
                if (c0 < D) w0 = We[n * D + c0];
                if (c1 < D) w1 = We[n * D + c1];
            } else if (n < NC1) {
                if (c0 < D) w0 = whh[(n - 600) * D + c0];
                if (c1 < D) w1 = whh[(n - 600) * D + c1];
            }
        } else if (n < 450) {
            if (c0 < D) w0 = wih[n * D + c0];
            if (c1 < D) w1 = wih[n * D + c1];
        }
        uint32_t mid;
        uint32_t hi = split2(w0, w1, &mid);
        uint32_t val = hi_part ? hi : mid;
        if (!two) F1i[li] = val;
        else      F2i[li] = val;
        return;
    }
    idx -= (NB1 + NB2) * FBLK2;
    if (idx < NC1) bias1[idx] = (idx < 600) ? 0.f : bhh[idx - 600];
}

__global__ void copy_h(const float* __restrict__ nodes, float* __restrict__ h,
                       uint32_t* __restrict__ Ah, uint32_t* __restrict__ Am,
                       int n_nodes) {
    int idx = blockIdx.x * blockDim.x + threadIdx.x;
    if (idx >= n_nodes * 160) return;
    int node = idx / 160, i = idx - node * 160;
    float v = 0.f;
    if (i < D) {
        v = nodes[node * D + i];
        h[node * D + i] = v;
    }
    frag_write(Ah, Am, node, i, v);
}

__global__ void hist_kernel(const int* __restrict__ dst, const int* __restrict__ etype,
                            int* __restrict__ degt, int E) {
    int e = blockIdx.x * blockDim.x + threadIdx.x;
    if (e < E) atomicAdd(&degt[dst[e] * NT + etype[e]], 1);
}

__global__ void biasinc_kernel(const int* __restrict__ degt, const float* __restrict__ be,
                               float* __restrict__ biasinc, int n_nodes) {
    int idx = blockIdx.x * blockDim.x + threadIdx.x;
    if (idx >= n_nodes * D) return;
    int node = idx / D, i = idx - node * D;
    float s = 0.f;
#pragma unroll
    for (int t = 0; t < NT; ++t) s += (float)degt[node * NT + t] * be[t * D + i];
    biasinc[idx] = s;
}

// ---------- hierarchical scan ----------
__global__ void scan_blocks(const int* __restrict__ degt, int* __restrict__ rowptr,
                            int* __restrict__ bsum, int n) {
    __shared__ int wt[32];
    int tid = threadIdx.x, lane = tid & 31, wid = tid >> 5;
    int idx = blockIdx.x * 1024 + tid;
    int v = 0;
    if (idx < n)
        v = degt[idx * NT] + degt[idx * NT + 1] + degt[idx * NT + 2] + degt[idx * NT + 3];
    int x = v;
#pragma unroll
    for (int off = 1; off < 32; off <<= 1) {
        int y = __shfl_up_sync(0xffffffffu, x, off);
        if (lane >= off) x += y;
    }
    if (lane == 31) wt[wid] = x;
    __syncthreads();
    if (wid == 0) {
        int w = wt[lane], wx = w;
#pragma unroll
        for (int off = 1; off < 32; off <<= 1) {
            int y = __shfl_up_sync(0xffffffffu, wx, off);
            if (lane >= off) wx += y;
        }
        wt[lane] = wx - w;
    }
    __syncthreads();
    int excl = wt[wid] + x - v;
    if (idx < n) rowptr[idx] = excl;
    if (tid == 1023) bsum[blockIdx.x] = excl + v;
}
__global__ void scan_fix(int* __restrict__ bsum, int nb, int* __restrict__ rowptr, int n) {
    if (threadIdx.x == 0) {
        int run = 0;
        for (int b = 0; b < nb; ++b) { int t = bsum[b]; bsum[b] = run; run += t; }
        rowptr[n] = run;
    }
}
__global__ void scan_add(int* __restrict__ rowptr, int* __restrict__ cursor,
                         const int* __restrict__ bsum, int n) {
    int idx = blockIdx.x * blockDim.x + threadIdx.x;
    if (idx >= n) return;
    int r = rowptr[idx] + bsum[idx >> 10];
    rowptr[idx] = r;
    cursor[idx] = r;
}

__global__ void csr_fill(const int* __restrict__ src, const int* __restrict__ dst,
                         const int* __restrict__ etype, int* __restrict__ cursor,
                         int* __restrict__ ebase, int E) {
    int e = blockIdx.x * blockDim.x + threadIdx.x;
    if (e >= E) return;
    int pos = atomicAdd(&cursor[dst[e]], 1);
    ebase[pos] = src[e] * MLD + etype[e] * D;
}

// ---------- fp16 3-split GEMM with cp.async 3-stage smem pipeline ----------
// stage (16KB): [0,4K) A-hi slice, [4K,8K) A-mid, [8K,16K) B interleaved slice
#define STAGEB 16384
#define GEMM_SMEM (3 * STAGEB)

__device__ __forceinline__ void stage_copy(uint32_t dst, const uint32_t* abh,
                                           const uint32_t* abm, const uint32_t* fbi,
                                           int ks, int tid) {
    const uint32_t* sa = abh + ks * 1024 + tid * 4;
    const uint32_t* sb = abm + ks * 1024 + tid * 4;
    const uint32_t* sc = fbi + ks * 2048 + tid * 4;
    CP_ASYNC16(dst + tid * 16, sa);
    CP_ASYNC16(dst + 4096 + tid * 16, sb);
    CP_ASYNC16(dst + 8192 + tid * 16, sc);
    CP_ASYNC16(dst + 12288 + tid * 16, sc + 1024);
}

__global__ __launch_bounds__(256, 2) void gemm_f16(
    const uint32_t* __restrict__ Ah, const uint32_t* __restrict__ Am,
    const uint32_t* __restrict__ Fi,
    float* __restrict__ C, int ldc, int M, int N,
    const float* __restrict__ bias) {
    extern __shared__ uint8_t sm8[];
    uint32_t sbase = smem_u32(sm8);
    int tid = threadIdx.x;
    int lane = tid & 31, wid = tid >> 5;
    int wm = wid & 1, wn = wid >> 1;
    int m0 = blockIdx.y * 128, n0 = blockIdx.x * 128;

    const uint32_t* abh = Ah + (size_t)blockIdx.y * ABLK;
    const uint32_t* abm = Am + (size_t)blockIdx.y * ABLK;
    const uint32_t* fbi = Fi + (size_t)blockIdx.x * FBLK2;

    float acc[4][4][4];
#pragma unroll
    for (int i = 0; i < 4; ++i)
#pragma unroll
        for (int j = 0; j < 4; ++j)
#pragma unroll
            for (int r = 0; r < 4; ++r) acc[i][j][r] = 0.f;

    stage_copy(sbase, abh, abm, fbi, 0, tid);
    CP_COMMIT();
    stage_copy(sbase + STAGEB, abh, abm, fbi, 1, tid);
    CP_COMMIT();

#pragma unroll
    for (int ks = 0; ks < 10; ++ks) {
        CP_WAIT1();
        __syncthreads();
        if (ks + 2 < 10)
            stage_copy(sbase + ((ks + 2) % 3) * STAGEB, abh, abm, fbi, ks + 2, tid);
        CP_COMMIT();

        uint32_t b0 = sbase + (ks % 3) * STAGEB;
        uint32_t ah[4][4], am[4][4], bh[4][2], bm[4][2];
#pragma unroll
        for (int mt = 0; mt < 4; ++mt) {
            uint32_t off = b0 + (wm * 4 + mt) * 512 + lane * 16;
            asm volatile("ld.shared.v4.u32 {%0,%1,%2,%3}, [%4];"
                : "=r"(ah[mt][0]), "=r"(ah[mt][1]), "=r"(ah[mt][2]), "=r"(ah[mt][3])
                : "r"(off));
            asm volatile("ld.shared.v4.u32 {%0,%1,%2,%3}, [%4];"
                : "=r"(am[mt][0]), "=r"(am[mt][1]), "=r"(am[mt][2]), "=r"(am[mt][3])
                : "r"(off + 4096));
        }
#pragma unroll
        for (int nt = 0; nt < 4; ++nt) {
            uint32_t off = b0 + 8192 + ((wn * 4 + nt) * 32 + lane) * 16;
            uint32_t v0, v1, v2, v3;
            asm volatile("ld.shared.v4.u32 {%0,%1,%2,%3}, [%4];"
                : "=r"(v0), "=r"(v1), "=r"(v2), "=r"(v3) : "r"(off));
            bh[nt][0] = v0; bh[nt][1] = v1;
            bm[nt][0] = v2; bm[nt][1] = v3;
        }
#pragma unroll
        for (int mt = 0; mt < 4; ++mt)
#pragma unroll
            for (int nt = 0; nt < 4; ++nt) {
                mma_f16(acc[mt][nt], ah[mt], bm[nt]);
                mma_f16(acc[mt][nt], am[mt], bh[nt]);
                mma_f16(acc[mt][nt], ah[mt], bh[nt]);
            }
    }

    int gi_ = lane >> 2, ti = lane & 3;
#pragma unroll
    for (int mt = 0; mt < 4; ++mt) {
#pragma unroll
        for (int nt = 0; nt < 4; ++nt) {
            int row = m0 + wm * 64 + mt * 16 + gi_;
            int col = n0 + wn * 32 + nt * 8 + 2 * ti;
            if (col >= N) continue;
            float b0 = bias[col], b1 = bias[col + 1];
            if (row < M) {
                float2 v = make_float2(acc[mt][nt][0] + b0, acc[mt][nt][1] + b1);
                *(float2*)&C[(size_t)row * ldc + col] = v;
            }
            if (row + 8 < M) {
                float2 v = make_float2(acc[mt][nt][2] + b0, acc[mt][nt][3] + b1);
                *(float2*)&C[(size_t)(row + 8) * ldc + col] = v;
            }
        }
    }
}

// ---------- CSR gather-aggregate, writes inc fragments ----------
__global__ void aggregate(const float* __restrict__ m, const float* __restrict__ biasinc,
                          const int* __restrict__ rowptr, const int* __restrict__ ebase,
                          uint32_t* __restrict__ Ih, uint32_t* __restrict__ Im) {
    int node = blockIdx.x;
    int i = threadIdx.x;
    float acc = 0.f;
    if (i < D) {
        int s = rowptr[node], e = rowptr[node + 1];
        acc = biasinc[(size_t)node * D + i];
        int p = s;
        for (; p + 3 < e; p += 4) {
            int b0 = ebase[p], b1 = ebase[p + 1], b2 = ebase[p + 2], b3 = ebase[p + 3];
            float v0 = m[(size_t)b0 + i];
            float v1 = m[(size_t)b1 + i];
            float v2 = m[(size_t)b2 + i];
            float v3 = m[(size_t)b3 + i];
            acc += (v0 + v1) + (v2 + v3);
        }
        for (; p < e; ++p) acc += m[(size_t)ebase[p] + i];
    }
    frag_write(Ih, Im, node, i, acc);
}

// ---------- GRU elementwise ----------
__global__ void gru_kernel(const float* __restrict__ gi, const float* __restrict__ o1,
                           float* __restrict__ h,
                           uint32_t* __restrict__ Ah, uint32_t* __restrict__ Am,
                           int n_nodes) {
    int idx = blockIdx.x * blockDim.x + threadIdx.x;
    if (idx >= n_nodes * 160) return;
    int node = idx / 160, i = idx - node * 160;
    float nh = 0.f;
    if (i < D) {
        const float* gir = gi + (size_t)node * GILD;
        const float* ghr = o1 + (size_t)node * MLD + 600;
        float ir = gir[i], iz = gir[D + i], inn = gir[2 * D + i];
        float hr = ghr[i], hz = ghr[D + i], hn = ghr[2 * D + i];
        float r = 1.f / (1.f + expf(-(ir + hr)));
        float z = 1.f / (1.f + expf(-(iz + hz)));
        float nn = tanhf(inn + r * hn);
        size_t hidx = (size_t)node * D + i;
        nh = (1.f - z) * nn + z * h[hidx];
        h[hidx] = nh;
    }
    frag_write(Ah, Am, node, i, nh);
}

// ---------- readout + MLP ----------
__global__ void gstart_init(int* __restrict__ gstart, int n_nodes) {
    int g = threadIdx.x;
    if (g <= NG) gstart[g] = (g == NG) ? n_nodes : 0x7fffffff;
}
__global__ void gstart_min(const int* __restrict__ gids, int* __restrict__ gstart, int n) {
    int i = blockIdx.x * blockDim.x + threadIdx.x;
    if (i < n) atomicMin(&gstart[gids[i]], i);
}
__global__ void gstart_fix(int* __restrict__ gstart) {
    if (threadIdx.x == 0)
        for (int g = NG - 1; g >= 0; --g)
            if (gstart[g] == 0x7fffffff) gstart[g] = gstart[g + 1];
}
__global__ void readout(const float* __restrict__ h, const int* __restrict__ gstart,
                        const float* __restrict__ pclass, float* __restrict__ x) {
    int g = blockIdx.x, i = threadIdx.x;
    int s = gstart[g], e = gstart[g + 1];
    if (i < D) {
        float acc = 0.f;
        for (int n = s; n < e; ++n) acc += h[(size_t)n * D + i];
        float l = logf(acc);
        if (l != l) l = 0.f;
        l = fmaxf(l, 0.f);
        x[g * XLD + i] = l;
    }
    if (i == D) x[g * XLD + D] = pclass[g];
}
__global__ void mlp_kernel(const float* __restrict__ x,
                           const float* __restrict__ fc1w, const float* __restrict__ fc1b,
                           const float* __restrict__ fc2w, const float* __restrict__ fc2b,
                           float* __restrict__ out) {
    __shared__ float xb[D + 1];
    __shared__ float hid[HIDN];
    int g = blockIdx.x, t = threadIdx.x;
    if (t < D + 1) xb[t] = x[g * XLD + t];
    __syncthreads();
    float acc = fc1b[t];
    for (int k = 0; k < D + 1; ++k) acc += xb[k] * fc1w[k * HIDN + t];
    hid[t] = acc > 0.f ? acc : 0.01f * acc;
    __syncthreads();
    if (t < 10) {
        float o = fc2b[t];
        for (int k = 0; k < HIDN; ++k) o += hid[k] * fc2w[k * 10 + t];
        out[g * 10 + t] = o;
    }
}

// ---------- launch ----------
extern "C" void kernel_launch(void* const* d_in, const int* in_sizes, int n_in,
                              void* d_out, int out_size) {
    const float* nodes  = (const float*)d_in[0];
    const float* pclass = (const float*)d_in[1];
    const int*   esrc   = (const int*)d_in[2];
    const int*   edst   = (const int*)d_in[3];
    const int*   etype  = (const int*)d_in[4];
    const int*   gids   = (const int*)d_in[5];
    const float* We     = (const float*)d_in[6];
    const float* be     = (const float*)d_in[7];
    const float* wih    = (const float*)d_in[8];
    const float* whh    = (const float*)d_in[9];
    const float* bih    = (const float*)d_in[10];
    const float* bhh    = (const float*)d_in[11];
    const float* fc1w   = (const float*)d_in[12];
    const float* fc1b   = (const float*)d_in[13];
    const float* fc2w   = (const float*)d_in[14];
    const float* fc2b   = (const float*)d_in[15];
    float* out = (float*)d_out;

    int n_nodes = in_sizes[0] / D;
    int E = in_sizes[2];

    float *h_p, *o1_p, *gi_p, *bi_p, *b1_p, *x_p;
    uint32_t *ah_p, *am_p, *ih_p, *im_p, *f1i_p, *f2i_p;
    int *degt_p, *rowptr_p, *cursor_p, *bsum_p, *ebase_p, *gstart_p;
    cudaGetSymbolAddress((void**)&h_p, g_h);
    cudaGetSymbolAddress((void**)&o1_p, g_out1);
    cudaGetSymbolAddress((void**)&gi_p, g_gi);
    cudaGetSymbolAddress((void**)&bi_p, g_biasinc);
    cudaGetSymbolAddress((void**)&ah_p, g_Ah);
    cudaGetSymbolAddress((void**)&am_p, g_Am);
    cudaGetSymbolAddress((void**)&ih_p, g_Ih);
    cudaGetSymbolAddress((void**)&im_p, g_Im);
    cudaGetSymbolAddress((void**)&f1i_p, g_F1i);
    cudaGetSymbolAddress((void**)&f2i_p, g_F2i);
    cudaGetSymbolAddress((void**)&b1_p, g_bias1);
    cudaGetSymbolAddress((void**)&x_p, g_x);
    cudaGetSymbolAddress((void**)&degt_p, g_degt);
    cudaGetSymbolAddress((void**)&rowptr_p, g_rowptr);
    cudaGetSymbolAddress((void**)&cursor_p, g_cursor);
    cudaGetSymbolAddress((void**)&bsum_p, g_bsum);
    cudaGetSymbolAddress((void**)&ebase_p, g_ebase);
    cudaGetSymbolAddress((void**)&gstart_p, g_gstart);

    cudaFuncSetAttribute(gemm_f16, cudaFuncAttributeMaxDynamicSharedMemorySize, GEMM_SMEM);

    int setup_items = NN * NT + (NB1 + NB2) * FBLK2 + NC1;
    setup_weights<<<(setup_items + 255) / 256, 256>>>(We, whh, wih, bhh,
        f1i_p, f2i_p, b1_p, degt_p);
    copy_h<<<(n_nodes * 160 + 255) / 256, 256>>>(nodes, h_p, ah_p, am_p, n_nodes);
    hist_kernel<<<(E + 255) / 256, 256>>>(edst, etype, degt_p, E);
    int nb = (n_nodes + 1023) / 1024;
    scan_blocks<<<nb, 1024>>>(degt_p, rowptr_p, bsum_p, n_nodes);
    scan_fix<<<1, 32>>>(bsum_p, nb, rowptr_p, n_nodes);
    scan_add<<<(n_nodes + 255) / 256, 256>>>(rowptr_p, cursor_p, bsum_p, n_nodes);
    biasinc_kernel<<<(n_nodes * D + 255) / 256, 256>>>(degt_p, be, bi_p, n_nodes);
    csr_fill<<<(E + 255) / 256, 256>>>(esrc, edst, etype, cursor_p, ebase_p, E);

    int nby = (n_nodes + 127) / 128;
    dim3 g1(NB1, nby);
    dim3 g2(NB2, nby);

    for (int p = 0; p < PASSES; ++p) {
        gemm_f16<<<g1, 256, GEMM_SMEM>>>(ah_p, am_p, f1i_p, o1_p, MLD, n_nodes, NC1, b1_p);
        aggregate<<<n_nodes, 160>>>(o1_p, bi_p, rowptr_p, ebase_p, ih_p, im_p);
        gemm_f16<<<g2, 256, GEMM_SMEM>>>(ih_p, im_p, f2i_p, gi_p, GILD, n_nodes, 450, bih);
        gru_kernel<<<(n_nodes * 160 + 255) / 256, 256>>>(gi_p, o1_p, h_p, ah_p, am_p, n_nodes);
    }

    gstart_init<<<1, NG + 1>>>(gstart_p, n_nodes);
    gstart_min<<<(n_nodes + 255) / 256, 256>>>(gids, gstart_p, n_nodes);
    gstart_fix<<<1, 1>>>(gstart_p);
    readout<<<NG, 160>>>(h_p, gstart_p, pclass, x_p);
    mlp_kernel<<<NG, HIDN>>>(x_p, fc1w, fc1b, fc2w, fc2b, out);
}

// round 11
// speedup vs baseline: 1.2414x; 1.2414x over previous
#include <cuda_runtime.h>
#include <cuda_fp16.h>
#include <math.h>
#include <stdint.h>

#define NN 100000
#define NE 800000
#define NG 64
#define NT 4
#define D 150
#define HIDN 512
#define PASSES 5
#define NC1 1050
#define MLD 1056
#define GILD 456
#define XLD 152
#define NB1 9
#define NB2 4
#define NBM 782
#define FBLK (10 * 16 * 32 * 2)    // u32 per B column block (hi or mid array)
#define ABLK (10 * 8 * 128)        // u32 per A row block (hi or mid array)

__device__ float g_h[(size_t)NN * D];
__device__ float g_out1[(size_t)NN * MLD];
__device__ float g_gi[(size_t)NN * GILD];
__device__ float g_biasinc[(size_t)NN * D];
__device__ uint32_t g_Ah[(size_t)NBM * ABLK];
__device__ uint32_t g_Am[(size_t)NBM * ABLK];
__device__ uint32_t g_Ih[(size_t)NBM * ABLK];
__device__ uint32_t g_Im[(size_t)NBM * ABLK];
__device__ uint32_t g_F1h[NB1 * FBLK];
__device__ uint32_t g_F1m[NB1 * FBLK];
__device__ uint32_t g_F2h[NB2 * FBLK];
__device__ uint32_t g_F2m[NB2 * FBLK];
__device__ float g_bias1[NC1];
__device__ int   g_degt[NN * NT];
__device__ int   g_rowptr[NN + 1];
__device__ int   g_cursor[NN];
__device__ int   g_bsum[128];
__device__ int   g_ebase[NE];
__device__ int   g_gstart[NG + 1];
__device__ float g_x[NG * XLD];

__device__ __forceinline__ uint32_t packh(float x0, float x1) {
    __half2 h = __floats2half2_rn(x0, x1);
    return *reinterpret_cast<uint32_t*>(&h);
}
__device__ __forceinline__ uint32_t split2(float x0, float x1, uint32_t* mid) {
    __half h0 = __float2half_rn(x0), h1 = __float2half_rn(x1);
    float m0 = x0 - __half2float(h0), m1 = x1 - __half2float(h1);
    *mid = packh(m0, m1);
    __half2 hh = __halves2half2(h0, h1);
    return *reinterpret_cast<uint32_t*>(&hh);
}
__device__ __forceinline__ void mma_f16(float* d, const uint32_t* a, const uint32_t* b) {
    asm volatile(
        "mma.sync.aligned.m16n8k16.row.col.f32.f16.f16.f32 "
        "{%0,%1,%2,%3}, {%4,%5,%6,%7}, {%8,%9}, {%0,%1,%2,%3};"
        : "+f"(d[0]), "+f"(d[1]), "+f"(d[2]), "+f"(d[3])
        : "r"(a[0]), "r"(a[1]), "r"(a[2]), "r"(a[3]), "r"(b[0]), "r"(b[1]));
}

// A fragment addressing (producer side)
__device__ __forceinline__ size_t frag_hidx(int node, int i) {
    int rb = node >> 7, mt = (node >> 4) & 7, r = node & 15;
    int ks = i >> 4, kk = i & 15, w = kk >> 1;
    int lane = (r & 7) * 4 + (w & 3);
    int reg = (r >> 3) + 2 * (w >> 2);
    size_t u32i = (((size_t)rb * 10 + ks) * 8 + mt) * 128 + lane * 4 + reg;
    return u32i * 2 + (i & 1);
}
__device__ __forceinline__ void frag_write(uint32_t* Fh, uint32_t* Fm, int node, int i, float v) {
    __half hi = __float2half_rn(v);
    __half mid = __float2half_rn(v - __half2float(hi));
    size_t fi = frag_hidx(node, i);
    ((__half*)Fh)[fi] = hi;
    ((__half*)Fm)[fi] = mid;
}

// ---------- setup: zero degt, fragment-ordered split weights, bias1 ----------
__global__ void setup_weights(const float* __restrict__ We, const float* __restrict__ whh,
                              const float* __restrict__ wih, const float* __restrict__ bhh,
                              uint32_t* __restrict__ F1h, uint32_t* __restrict__ F1m,
                              uint32_t* __restrict__ F2h, uint32_t* __restrict__ F2m,
                              float* __restrict__ bias1, int* __restrict__ degt) {
    int idx = blockIdx.x * blockDim.x + threadIdx.x;
    if (idx < NN * NT) { degt[idx] = 0; return; }
    idx -= NN * NT;
    if (idx < (NB1 + NB2) * FBLK) {
        int two = (idx >= NB1 * FBLK);
        int li = two ? idx - NB1 * FBLK : idx;
        int blk = li / FBLK, r = li % FBLK;
        int ks = r >> 10, r2 = r & 1023;
        int nt = r2 >> 6, r3 = r2 & 63;
        int lane = r3 >> 1, reg = r3 & 1;
        int n = blk * 128 + nt * 8 + (lane >> 2);
        int w = ks * 8 + reg * 4 + (lane & 3);
        int c0 = 2 * w, c1 = c0 + 1;
        float w0 = 0.f, w1 = 0.f;
        if (!two) {
            if (n < 600) {
                if (c0 < D) w0 = We[n * D + c0];
                if (c1 < D) w1 = We[n * D + c1];
            } else if (n < NC1) {
                if (c0 < D) w0 = whh[(n - 600) * D + c0];
                if (c1 < D) w1 = whh[(n - 600) * D + c1];
            }
        } else if (n < 450) {
            if (c0 < D) w0 = wih[n * D + c0];
            if (c1 < D) w1 = wih[n * D + c1];
        }
        uint32_t mid;
        uint32_t hi = split2(w0, w1, &mid);
        if (!two) { F1h[li] = hi; F1m[li] = mid; }
        else      { F2h[li] = hi; F2m[li] = mid; }
        return;
    }
    idx -= (NB1 + NB2) * FBLK;
    if (idx < NC1) bias1[idx] = (idx < 600) ? 0.f : bhh[idx - 600];
}

__global__ void copy_h(const float* __restrict__ nodes, float* __restrict__ h,
                       uint32_t* __restrict__ Ah, uint32_t* __restrict__ Am,
                       int n_nodes) {
    int idx = blockIdx.x * blockDim.x + threadIdx.x;
    if (idx >= n_nodes * 160) return;
    int node = idx / 160, i = idx - node * 160;
    float v = 0.f;
    if (i < D) {
        v = nodes[node * D + i];
        h[node * D + i] = v;
    }
    frag_write(Ah, Am, node, i, v);
}

__global__ void hist_kernel(const int* __restrict__ dst, const int* __restrict__ etype,
                            int* __restrict__ degt, int E) {
    int e = blockIdx.x * blockDim.x + threadIdx.x;
    if (e < E) atomicAdd(&degt[dst[e] * NT + etype[e]], 1);
}

__global__ void biasinc_kernel(const int* __restrict__ degt, const float* __restrict__ be,
                               float* __restrict__ biasinc, int n_nodes) {
    int idx = blockIdx.x * blockDim.x + threadIdx.x;
    if (idx >= n_nodes * D) return;
    int node = idx / D, i = idx - node * D;
    float s = 0.f;
#pragma unroll
    for (int t = 0; t < NT; ++t) s += (float)degt[node * NT + t] * be[t * D + i];
    biasinc[idx] = s;
}

// ---------- hierarchical scan ----------
__global__ void scan_blocks(const int* __restrict__ degt, int* __restrict__ rowptr,
                            int* __restrict__ bsum, int n) {
    __shared__ int wt[32];
    int tid = threadIdx.x, lane = tid & 31, wid = tid >> 5;
    int idx = blockIdx.x * 1024 + tid;
    int v = 0;
    if (idx < n)
        v = degt[idx * NT] + degt[idx * NT + 1] + degt[idx * NT + 2] + degt[idx * NT + 3];
    int x = v;
#pragma unroll
    for (int off = 1; off < 32; off <<= 1) {
        int y = __shfl_up_sync(0xffffffffu, x, off);
        if (lane >= off) x += y;
    }
    if (lane == 31) wt[wid] = x;
    __syncthreads();
    if (wid == 0) {
        int w = wt[lane], wx = w;
#pragma unroll
        for (int off = 1; off < 32; off <<= 1) {
            int y = __shfl_up_sync(0xffffffffu, wx, off);
            if (lane >= off) wx += y;
        }
        wt[lane] = wx - w;
    }
    __syncthreads();
    int excl = wt[wid] + x - v;
    if (idx < n) rowptr[idx] = excl;
    if (tid == 1023) bsum[blockIdx.x] = excl + v;
}
__global__ void scan_fix(int* __restrict__ bsum, int nb, int* __restrict__ rowptr, int n) {
    if (threadIdx.x == 0) {
        int run = 0;
        for (int b = 0; b < nb; ++b) { int t = bsum[b]; bsum[b] = run; run += t; }
        rowptr[n] = run;
    }
}
__global__ void scan_add(int* __restrict__ rowptr, int* __restrict__ cursor,
                         const int* __restrict__ bsum, int n) {
    int idx = blockIdx.x * blockDim.x + threadIdx.x;
    if (idx >= n) return;
    int r = rowptr[idx] + bsum[idx >> 10];
    rowptr[idx] = r;
    cursor[idx] = r;
}

__global__ void csr_fill(const int* __restrict__ src, const int* __restrict__ dst,
                         const int* __restrict__ etype, int* __restrict__ cursor,
                         int* __restrict__ ebase, int E) {
    int e = blockIdx.x * blockDim.x + threadIdx.x;
    if (e >= E) return;
    int pos = atomicAdd(&cursor[dst[e]], 1);
    ebase[pos] = src[e] * MLD + etype[e] * D;
}

// ---------- fp16 3-split GEMM: all operands fragment-ordered in gmem, no smem
__global__ __launch_bounds__(256, 2) void gemm_f16(
    const uint32_t* __restrict__ Ah, const uint32_t* __restrict__ Am,
    const uint32_t* __restrict__ Fh, const uint32_t* __restrict__ Fm,
    float* __restrict__ C, int ldc, int M, int N,
    const float* __restrict__ bias) {
    int tid = threadIdx.x;
    int lane = tid & 31, wid = tid >> 5;
    int wm = wid & 1, wn = wid >> 1;
    int m0 = blockIdx.y * 128, n0 = blockIdx.x * 128;

    float acc[4][4][4];
#pragma unroll
    for (int i = 0; i < 4; ++i)
#pragma unroll
        for (int j = 0; j < 4; ++j)
#pragma unroll
            for (int r = 0; r < 4; ++r) acc[i][j][r] = 0.f;

    const uint32_t* abh = Ah + (size_t)blockIdx.y * ABLK;
    const uint32_t* abm = Am + (size_t)blockIdx.y * ABLK;
    const uint32_t* fbh = Fh + (size_t)blockIdx.x * FBLK;
    const uint32_t* fbm = Fm + (size_t)blockIdx.x * FBLK;

#pragma unroll
    for (int ks = 0; ks < 10; ++ks) {
        uint32_t ah[4][4], am[4][4], bh[4][2], bm[4][2];
#pragma unroll
        for (int mt = 0; mt < 4; ++mt) {
            size_t o = (((size_t)ks * 8) + wm * 4 + mt) * 128 + lane * 4;
            uint4 t = __ldg((const uint4*)(abh + o));
            ah[mt][0] = t.x; ah[mt][1] = t.y; ah[mt][2] = t.z; ah[mt][3] = t.w;
            uint4 u = __ldg((const uint4*)(abm + o));
            am[mt][0] = u.x; am[mt][1] = u.y; am[mt][2] = u.z; am[mt][3] = u.w;
        }
#pragma unroll
        for (int nt = 0; nt < 4; ++nt) {
            size_t o = (((size_t)ks * 16 + wn * 4 + nt) * 32 + lane) * 2;
            uint2 t = __ldg((const uint2*)(fbh + o));
            bh[nt][0] = t.x; bh[nt][1] = t.y;
            uint2 u = __ldg((const uint2*)(fbm + o));
            bm[nt][0] = u.x; bm[nt][1] = u.y;
        }
#pragma unroll
        for (int mt = 0; mt < 4; ++mt)
#pragma unroll
            for (int nt = 0; nt < 4; ++nt) {
                mma_f16(acc[mt][nt], ah[mt], bm[nt]);
                mma_f16(acc[mt][nt], am[mt], bh[nt]);
                mma_f16(acc[mt][nt], ah[mt], bh[nt]);
            }
    }

    int gi_ = lane >> 2, ti = lane & 3;
#pragma unroll
    for (int mt = 0; mt < 4; ++mt) {
#pragma unroll
        for (int nt = 0; nt < 4; ++nt) {
            int row = m0 + wm * 64 + mt * 16 + gi_;
            int col = n0 + wn * 32 + nt * 8 + 2 * ti;
            if (col >= N) continue;
            float b0 = bias[col], b1 = bias[col + 1];
            if (row < M) {
                float2 v = make_float2(acc[mt][nt][0] + b0, acc[mt][nt][1] + b1);
                *(float2*)&C[(size_t)row * ldc + col] = v;
            }
            if (row + 8 < M) {
                float2 v = make_float2(acc[mt][nt][2] + b0, acc[mt][nt][3] + b1);
                *(float2*)&C[(size_t)(row + 8) * ldc + col] = v;
            }
        }
    }
}

// ---------- CSR gather-aggregate, writes inc fragments directly ----------
__global__ void aggregate(const float* __restrict__ m, const float* __restrict__ biasinc,
                          const int* __restrict__ rowptr, const int* __restrict__ ebase,
                          uint32_t* __restrict__ Ih, uint32_t* __restrict__ Im) {
    int node = blockIdx.x;
    int i = threadIdx.x;
    float acc = 0.f;
    if (i < D) {
        int s = rowptr[node], e = rowptr[node + 1];
        acc = biasinc[(size_t)node * D + i];
        int p = s;
        for (; p + 3 < e; p += 4) {
            int b0 = ebase[p], b1 = ebase[p + 1], b2 = ebase[p + 2], b3 = ebase[p + 3];
            float v0 = m[(size_t)b0 + i];
            float v1 = m[(size_t)b1 + i];
            float v2 = m[(size_t)b2 + i];
            float v3 = m[(size_t)b3 + i];
            acc += (v0 + v1) + (v2 + v3);
        }
        for (; p < e; ++p) acc += m[(size_t)ebase[p] + i];
    }
    frag_write(Ih, Im, node, i, acc);
}

// ---------- GRU elementwise ----------
__global__ void gru_kernel(const float* __restrict__ gi, const float* __restrict__ o1,
                           float* __restrict__ h,
                           uint32_t* __restrict__ Ah, uint32_t* __restrict__ Am,
                           int n_nodes) {
    int idx = blockIdx.x * blockDim.x + threadIdx.x;
    if (idx >= n_nodes * 160) return;
    int node = idx / 160, i = idx - node * 160;
    float nh = 0.f;
    if (i < D) {
        const float* gir = gi + (size_t)node * GILD;
        const float* ghr = o1 + (size_t)node * MLD + 600;
        float ir = gir[i], iz = gir[D + i], inn = gir[2 * D + i];
        float hr = ghr[i], hz = ghr[D + i], hn = ghr[2 * D + i];
        float r = 1.f / (1.f + expf(-(ir + hr)));
        float z = 1.f / (1.f + expf(-(iz + hz)));
        float nn = tanhf(inn + r * hn);
        size_t hidx = (size_t)node * D + i;
        nh = (1.f - z) * nn + z * h[hidx];
        h[hidx] = nh;
    }
    frag_write(Ah, Am, node, i, nh);
}

// ---------- readout + MLP ----------
__global__ void gstart_init(int* __restrict__ gstart, int n_nodes) {
    int g = threadIdx.x;
    if (g <= NG) gstart[g] = (g == NG) ? n_nodes : 0x7fffffff;
}
__global__ void gstart_min(const int* __restrict__ gids, int* __restrict__ gstart, int n) {
    int i = blockIdx.x * blockDim.x + threadIdx.x;
    if (i < n) atomicMin(&gstart[gids[i]], i);
}
__global__ void gstart_fix(int* __restrict__ gstart) {
    if (threadIdx.x == 0)
        for (int g = NG - 1; g >= 0; --g)
            if (gstart[g] == 0x7fffffff) gstart[g] = gstart[g + 1];
}
__global__ void readout(const float* __restrict__ h, const int* __restrict__ gstart,
                        const float* __restrict__ pclass, float* __restrict__ x) {
    int g = blockIdx.x, i = threadIdx.x;
    int s = gstart[g], e = gstart[g + 1];
    if (i < D) {
        float acc = 0.f;
        for (int n = s; n < e; ++n) acc += h[(size_t)n * D + i];
        float l = logf(acc);
        if (l != l) l = 0.f;
        l = fmaxf(l, 0.f);
        x[g * XLD + i] = l;
    }
    if (i == D) x[g * XLD + D] = pclass[g];
}
__global__ void mlp_kernel(const float* __restrict__ x,
                           const float* __restrict__ fc1w, const float* __restrict__ fc1b,
                           const float* __restrict__ fc2w, const float* __restrict__ fc2b,
                           float* __restrict__ out) {
    __shared__ float xb[D + 1];
    __shared__ float hid[HIDN];
    int g = blockIdx.x, t = threadIdx.x;
    if (t < D + 1) xb[t] = x[g * XLD + t];
    __syncthreads();
    float acc = fc1b[t];
    for (int k = 0; k < D + 1; ++k) acc += xb[k] * fc1w[k * HIDN + t];
    hid[t] = acc > 0.f ? acc : 0.01f * acc;
    __syncthreads();
    if (t < 10) {
        float o = fc2b[t];
        for (int k = 0; k < HIDN; ++k) o += hid[k] * fc2w[k * 10 + t];
        out[g * 10 + t] = o;
    }
}

// ---------- launch ----------
extern "C" void kernel_launch(void* const* d_in, const int* in_sizes, int n_in,
                              void* d_out, int out_size) {
    const float* nodes  = (const float*)d_in[0];
    const float* pclass = (const float*)d_in[1];
    const int*   esrc   = (const int*)d_in[2];
    const int*   edst   = (const int*)d_in[3];
    const int*   etype  = (const int*)d_in[4];
    const int*   gids   = (const int*)d_in[5];
    const float* We     = (const float*)d_in[6];
    const float* be     = (const float*)d_in[7];
    const float* wih    = (const float*)d_in[8];
    const float* whh    = (const float*)d_in[9];
    const float* bih    = (const float*)d_in[10];
    const float* bhh    = (const float*)d_in[11];
    const float* fc1w   = (const float*)d_in[12];
    const float* fc1b   = (const float*)d_in[13];
    const float* fc2w   = (const float*)d_in[14];
    const float* fc2b   = (const float*)d_in[15];
    float* out = (float*)d_out;

    int n_nodes = in_sizes[0] / D;
    int E = in_sizes[2];

    float *h_p, *o1_p, *gi_p, *bi_p, *b1_p, *x_p;
    uint32_t *ah_p, *am_p, *ih_p, *im_p, *f1h_p, *f1m_p, *f2h_p, *f2m_p;
    int *degt_p, *rowptr_p, *cursor_p, *bsum_p, *ebase_p, *gstart_p;
    cudaGetSymbolAddress((void**)&h_p, g_h);
    cudaGetSymbolAddress((void**)&o1_p, g_out1);
    cudaGetSymbolAddress((void**)&gi_p, g_gi);
    cudaGetSymbolAddress((void**)&bi_p, g_biasinc);
    cudaGetSymbolAddress((void**)&ah_p, g_Ah);
    cudaGetSymbolAddress((void**)&am_p, g_Am);
    cudaGetSymbolAddress((void**)&ih_p, g_Ih);
    cudaGetSymbolAddress((void**)&im_p, g_Im);
    cudaGetSymbolAddress((void**)&f1h_p, g_F1h);
    cudaGetSymbolAddress((void**)&f1m_p, g_F1m);
    cudaGetSymbolAddress((void**)&f2h_p, g_F2h);
    cudaGetSymbolAddress((void**)&f2m_p, g_F2m);
    cudaGetSymbolAddress((void**)&b1_p, g_bias1);
    cudaGetSymbolAddress((void**)&x_p, g_x);
    cudaGetSymbolAddress((void**)&degt_p, g_degt);
    cudaGetSymbolAddress((void**)&rowptr_p, g_rowptr);
    cudaGetSymbolAddress((void**)&cursor_p, g_cursor);
    cudaGetSymbolAddress((void**)&bsum_p, g_bsum);
    cudaGetSymbolAddress((void**)&ebase_p, g_ebase);
    cudaGetSymbolAddress((void**)&gstart_p, g_gstart);

    int setup_items = NN * NT + (NB1 + NB2) * FBLK + NC1;
    setup_weights<<<(setup_items + 255) / 256, 256>>>(We, whh, wih, bhh,
        f1h_p, f1m_p, f2h_p, f2m_p, b1_p, degt_p);
    copy_h<<<(n_nodes * 160 + 255) / 256, 256>>>(nodes, h_p, ah_p, am_p, n_nodes);
    hist_kernel<<<(E + 255) / 256, 256>>>(edst, etype, degt_p, E);
    int nb = (n_nodes + 1023) / 1024;
    scan_blocks<<<nb, 1024>>>(degt_p, rowptr_p, bsum_p, n_nodes);
    scan_fix<<<1, 32>>>(bsum_p, nb, rowptr_p, n_nodes);
    scan_add<<<(n_nodes + 255) / 256, 256>>>(rowptr_p, cursor_p, bsum_p, n_nodes);
    biasinc_kernel<<<(n_nodes * D + 255) / 256, 256>>>(degt_p, be, bi_p, n_nodes);
    csr_fill<<<(E + 255) / 256, 256>>>(esrc, edst, etype, cursor_p, ebase_p, E);

    int nby = (n_nodes + 127) / 128;
    dim3 g1(NB1, nby);
    dim3 g2(NB2, nby);

    for (int p = 0; p < PASSES; ++p) {
        gemm_f16<<<g1, 256>>>(ah_p, am_p, f1h_p, f1m_p, o1_p, MLD, n_nodes, NC1, b1_p);
        aggregate<<<n_nodes, 160>>>(o1_p, bi_p, rowptr_p, ebase_p, ih_p, im_p);
        gemm_f16<<<g2, 256>>>(ih_p, im_p, f2h_p, f2m_p, gi_p, GILD, n_nodes, 450, bih);
        gru_kernel<<<(n_nodes * 160 + 255) / 256, 256>>>(gi_p, o1_p, h_p, ah_p, am_p, n_nodes);
    }

    gstart_init<<<1, NG + 1>>>(gstart_p, n_nodes);
    gstart_min<<<(n_nodes + 255) / 256, 256>>>(gids, gstart_p, n_nodes);
    gstart_fix<<<1, 1>>>(gstart_p);
    readout<<<NG, 160>>>(h_p, gstart_p, pclass, x_p);
    mlp_kernel<<<NG, HIDN>>>(x_p, fc1w, fc1b, fc2w, fc2b, out);
}

// round 12
// speedup vs baseline: 1.2810x; 1.0319x over previous
#include <cuda_runtime.h>
#include <cuda_fp16.h>
#include <math.h>
#include <stdint.h>

#define NN 100000
#define NE 800000
#define NG 64
#define NT 4
#define D 150
#define HIDN 512
#define PASSES 5
#define NC1 1050
#define MLD 1056
#define GILD 456
#define XLD 152
#define NB1 9
#define NB2 4
#define NBM 782
#define FBLK2 20480                // u32 per B col block: 10ks x 16nt x 32lane x 4(hi0,hi1,mid0,mid1)
#define ABLK (10 * 8 * 128)        // u32 per A row block (hi or mid array)

__device__ float g_h[(size_t)NN * D];
__device__ float g_out1[(size_t)NN * MLD];
__device__ float g_gi[(size_t)NN * GILD];
__device__ float g_biasinc[(size_t)NN * D];
__device__ uint32_t g_Ah[(size_t)NBM * ABLK];
__device__ uint32_t g_Am[(size_t)NBM * ABLK];
__device__ uint32_t g_Ih[(size_t)NBM * ABLK];
__device__ uint32_t g_Im[(size_t)NBM * ABLK];
__device__ uint32_t g_F1i[NB1 * FBLK2];
__device__ uint32_t g_F2i[NB2 * FBLK2];
__device__ float g_bias1[NC1];
__device__ int   g_degt[NN * NT];
__device__ int   g_rowptr[NN + 1];
__device__ int   g_cursor[NN];
__device__ int   g_bsum[128];
__device__ int   g_ebase[NE];
__device__ int   g_gstart[NG + 1];
__device__ float g_x[NG * XLD];

__device__ __forceinline__ uint32_t packh(float x0, float x1) {
    __half2 h = __floats2half2_rn(x0, x1);
    return *reinterpret_cast<uint32_t*>(&h);
}
__device__ __forceinline__ uint32_t split2(float x0, float x1, uint32_t* mid) {
    __half h0 = __float2half_rn(x0), h1 = __float2half_rn(x1);
    float m0 = x0 - __half2float(h0), m1 = x1 - __half2float(h1);
    *mid = packh(m0, m1);
    __half2 hh = __halves2half2(h0, h1);
    return *reinterpret_cast<uint32_t*>(&hh);
}
__device__ __forceinline__ void mma_f16(float* d, const uint32_t* a, const uint32_t* b) {
    asm volatile(
        "mma.sync.aligned.m16n8k16.row.col.f32.f16.f16.f32 "
        "{%0,%1,%2,%3}, {%4,%5,%6,%7}, {%8,%9}, {%0,%1,%2,%3};"
        : "+f"(d[0]), "+f"(d[1]), "+f"(d[2]), "+f"(d[3])
        : "r"(a[0]), "r"(a[1]), "r"(a[2]), "r"(a[3]), "r"(b[0]), "r"(b[1]));
}

// word index for feature pair t (=i/2, t in 0..79) of node; matches MMA A fragment map
__device__ __forceinline__ size_t frag_widx(int node, int t) {
    int rb = node >> 7, mt = (node >> 4) & 7, r = node & 15;
    int ks = t >> 3;
    int lane = (r & 7) * 4 + (t & 3);
    int reg = (r >> 3) + 2 * ((t >> 2) & 1);
    return (((size_t)rb * 10 + ks) * 8 + mt) * 128 + lane * 4 + reg;
}
__device__ __forceinline__ void frag_write2(uint32_t* Fh, uint32_t* Fm,
                                            int node, int t, float v0, float v1) {
    uint32_t mid;
    uint32_t hi = split2(v0, v1, &mid);
    size_t wi = frag_widx(node, t);
    Fh[wi] = hi;
    Fm[wi] = mid;
}

// ---------- setup: zero degt, interleaved fragment weights, bias1 ----------
__global__ void setup_weights(const float* __restrict__ We, const float* __restrict__ whh,
                              const float* __restrict__ wih, const float* __restrict__ bhh,
                              uint32_t* __restrict__ F1i, uint32_t* __restrict__ F2i,
                              float* __restrict__ bias1, int* __restrict__ degt) {
    int idx = blockIdx.x * blockDim.x + threadIdx.x;
    if (idx < NN * NT) { degt[idx] = 0; return; }
    idx -= NN * NT;
    if (idx < (NB1 + NB2) * FBLK2) {
        int two = (idx >= NB1 * FBLK2);
        int li = two ? idx - NB1 * FBLK2 : idx;
        int blk = li / FBLK2, r = li % FBLK2;
        int ks = r >> 11, r2 = r & 2047;
        int nt = r2 >> 7, r3 = r2 & 127;
        int lane = r3 >> 2, q = r3 & 3;
        int reg = q & 1;
        int hi_part = (q < 2);
        int n = blk * 128 + nt * 8 + (lane >> 2);
        int w = ks * 8 + reg * 4 + (lane & 3);
        int c0 = 2 * w, c1 = c0 + 1;
        float w0 = 0.f, w1 = 0.f;
        if (!two) {
            if (n < 600) {
                if (c0 < D) w0 = We[n * D + c0];
                if (c1 < D) w1 = We[n * D + c1];
            } else if (n < NC1) {
                if (c0 < D) w0 = whh[(n - 600) * D + c0];
                if (c1 < D) w1 = whh[(n - 600) * D + c1];
            }
        } else if (n < 450) {
            if (c0 < D) w0 = wih[n * D + c0];
            if (c1 < D) w1 = wih[n * D + c1];
        }
        uint32_t mid;
        uint32_t hi = split2(w0, w1, &mid);
        uint32_t val = hi_part ? hi : mid;
        if (!two) F1i[li] = val;
        else      F2i[li] = val;
        return;
    }
    idx -= (NB1 + NB2) * FBLK2;
    if (idx < NC1) bias1[idx] = (idx < 600) ? 0.f : bhh[idx - 600];
}

// copy nodes -> h (compact) + h fragments (pair-granular)
__global__ void copy_h(const float* __restrict__ nodes, float* __restrict__ h,
                       uint32_t* __restrict__ Ah, uint32_t* __restrict__ Am,
                       int n_nodes) {
    int idx = blockIdx.x * blockDim.x + threadIdx.x;
    if (idx >= n_nodes * 80) return;
    int node = idx / 80, t = idx - node * 80;
    float v0 = 0.f, v1 = 0.f;
    if (t < 75) {
        float2 v = *(const float2*)(nodes + (size_t)node * D + 2 * t);
        v0 = v.x; v1 = v.y;
        *(float2*)(h + (size_t)node * D + 2 * t) = v;
    }
    frag_write2(Ah, Am, node, t, v0, v1);
}

__global__ void hist_kernel(const int* __restrict__ dst, const int* __restrict__ etype,
                            int* __restrict__ degt, int E) {
    int e = blockIdx.x * blockDim.x + threadIdx.x;
    if (e < E) atomicAdd(&degt[dst[e] * NT + etype[e]], 1);
}

__global__ void biasinc_kernel(const int* __restrict__ degt, const float* __restrict__ be,
                               float* __restrict__ biasinc, int n_nodes) {
    int idx = blockIdx.x * blockDim.x + threadIdx.x;
    if (idx >= n_nodes * D) return;
    int node = idx / D, i = idx - node * D;
    float s = 0.f;
#pragma unroll
    for (int t = 0; t < NT; ++t) s += (float)degt[node * NT + t] * be[t * D + i];
    biasinc[idx] = s;
}

// ---------- hierarchical scan ----------
__global__ void scan_blocks(const int* __restrict__ degt, int* __restrict__ rowptr,
                            int* __restrict__ bsum, int n) {
    __shared__ int wt[32];
    int tid = threadIdx.x, lane = tid & 31, wid = tid >> 5;
    int idx = blockIdx.x * 1024 + tid;
    int v = 0;
    if (idx < n)
        v = degt[idx * NT] + degt[idx * NT + 1] + degt[idx * NT + 2] + degt[idx * NT + 3];
    int x = v;
#pragma unroll
    for (int off = 1; off < 32; off <<= 1) {
        int y = __shfl_up_sync(0xffffffffu, x, off);
        if (lane >= off) x += y;
    }
    if (lane == 31) wt[wid] = x;
    __syncthreads();
    if (wid == 0) {
        int w = wt[lane], wx = w;
#pragma unroll
        for (int off = 1; off < 32; off <<= 1) {
            int y = __shfl_up_sync(0xffffffffu, wx, off);
            if (lane >= off) wx += y;
        }
        wt[lane] = wx - w;
    }
    __syncthreads();
    int excl = wt[wid] + x - v;
    if (idx < n) rowptr[idx] = excl;
    if (tid == 1023) bsum[blockIdx.x] = excl + v;
}
__global__ void scan_fix(int* __restrict__ bsum, int nb, int* __restrict__ rowptr, int n) {
    if (threadIdx.x == 0) {
        int run = 0;
        for (int b = 0; b < nb; ++b) { int t = bsum[b]; bsum[b] = run; run += t; }
        rowptr[n] = run;
    }
}
__global__ void scan_add(int* __restrict__ rowptr, int* __restrict__ cursor,
                         const int* __restrict__ bsum, int n) {
    int idx = blockIdx.x * blockDim.x + threadIdx.x;
    if (idx >= n) return;
    int r = rowptr[idx] + bsum[idx >> 10];
    rowptr[idx] = r;
    cursor[idx] = r;
}

__global__ void csr_fill(const int* __restrict__ src, const int* __restrict__ dst,
                         const int* __restrict__ etype, int* __restrict__ cursor,
                         int* __restrict__ ebase, int E) {
    int e = blockIdx.x * blockDim.x + threadIdx.x;
    if (e >= E) return;
    int pos = atomicAdd(&cursor[dst[e]], 1);
    ebase[pos] = src[e] * MLD + etype[e] * D;
}

// ---------- fp16 3-split GEMM: fragment-ordered gmem operands, B interleaved --
__global__ __launch_bounds__(256, 2) void gemm_f16(
    const uint32_t* __restrict__ Ah, const uint32_t* __restrict__ Am,
    const uint32_t* __restrict__ Fi,
    float* __restrict__ C, int ldc, int M, int N,
    const float* __restrict__ bias) {
    int tid = threadIdx.x;
    int lane = tid & 31, wid = tid >> 5;
    int wm = wid & 1, wn = wid >> 1;
    int m0 = blockIdx.y * 128, n0 = blockIdx.x * 128;

    float acc[4][4][4];
#pragma unroll
    for (int i = 0; i < 4; ++i)
#pragma unroll
        for (int j = 0; j < 4; ++j)
#pragma unroll
            for (int r = 0; r < 4; ++r) acc[i][j][r] = 0.f;

    const uint32_t* abh = Ah + (size_t)blockIdx.y * ABLK;
    const uint32_t* abm = Am + (size_t)blockIdx.y * ABLK;
    const uint32_t* fbi = Fi + (size_t)blockIdx.x * FBLK2;

#pragma unroll
    for (int ks = 0; ks < 10; ++ks) {
        uint32_t ah[4][4], am[4][4], bh[4][2], bm[4][2];
#pragma unroll
        for (int mt = 0; mt < 4; ++mt) {
            size_t o = (((size_t)ks * 8) + wm * 4 + mt) * 128 + lane * 4;
            uint4 t = __ldg((const uint4*)(abh + o));
            ah[mt][0] = t.x; ah[mt][1] = t.y; ah[mt][2] = t.z; ah[mt][3] = t.w;
            uint4 u = __ldg((const uint4*)(abm + o));
            am[mt][0] = u.x; am[mt][1] = u.y; am[mt][2] = u.z; am[mt][3] = u.w;
        }
#pragma unroll
        for (int nt = 0; nt < 4; ++nt) {
            size_t o = (((size_t)ks * 16 + wn * 4 + nt) * 32 + lane) * 4;
            uint4 t = __ldg((const uint4*)(fbi + o));
            bh[nt][0] = t.x; bh[nt][1] = t.y;
            bm[nt][0] = t.z; bm[nt][1] = t.w;
        }
#pragma unroll
        for (int mt = 0; mt < 4; ++mt)
#pragma unroll
            for (int nt = 0; nt < 4; ++nt) {
                mma_f16(acc[mt][nt], ah[mt], bm[nt]);
                mma_f16(acc[mt][nt], am[mt], bh[nt]);
                mma_f16(acc[mt][nt], ah[mt], bh[nt]);
            }
    }

    int gi_ = lane >> 2, ti = lane & 3;
#pragma unroll
    for (int mt = 0; mt < 4; ++mt) {
#pragma unroll
        for (int nt = 0; nt < 4; ++nt) {
            int row = m0 + wm * 64 + mt * 16 + gi_;
            int col = n0 + wn * 32 + nt * 8 + 2 * ti;
            if (col >= N) continue;
            float b0 = bias[col], b1 = bias[col + 1];
            if (row < M) {
                float2 v = make_float2(acc[mt][nt][0] + b0, acc[mt][nt][1] + b1);
                *(float2*)&C[(size_t)row * ldc + col] = v;
            }
            if (row + 8 < M) {
                float2 v = make_float2(acc[mt][nt][2] + b0, acc[mt][nt][3] + b1);
                *(float2*)&C[(size_t)(row + 8) * ldc + col] = v;
            }
        }
    }
}

// ---------- CSR gather-aggregate (pair-granular), writes inc fragments ------
__global__ void aggregate(const float* __restrict__ m, const float* __restrict__ biasinc,
                          const int* __restrict__ rowptr, const int* __restrict__ ebase,
                          uint32_t* __restrict__ Ih, uint32_t* __restrict__ Im) {
    int node = blockIdx.x;
    int t = threadIdx.x;   // 0..79, feature pair index
    float a0 = 0.f, a1 = 0.f;
    if (t < 75) {
        float2 b = *(const float2*)(biasinc + (size_t)node * D + 2 * t);
        a0 = b.x; a1 = b.y;
        int s = rowptr[node], e = rowptr[node + 1];
        int p = s;
        for (; p + 3 < e; p += 4) {
            int b0 = ebase[p], b1 = ebase[p + 1], b2 = ebase[p + 2], b3 = ebase[p + 3];
            float2 v0 = __ldg((const float2*)(m + b0) + t);
            float2 v1 = __ldg((const float2*)(m + b1) + t);
            float2 v2 = __ldg((const float2*)(m + b2) + t);
            float2 v3 = __ldg((const float2*)(m + b3) + t);
            a0 += (v0.x + v1.x) + (v2.x + v3.x);
            a1 += (v0.y + v1.y) + (v2.y + v3.y);
        }
        for (; p < e; ++p) {
            float2 v = __ldg((const float2*)(m + ebase[p]) + t);
            a0 += v.x; a1 += v.y;
        }
    }
    frag_write2(Ih, Im, node, t, a0, a1);
}

// ---------- GRU elementwise (pair-granular) ----------
__global__ void gru_kernel(const float* __restrict__ gi, const float* __restrict__ o1,
                           float* __restrict__ h,
                           uint32_t* __restrict__ Ah, uint32_t* __restrict__ Am,
                           int n_nodes) {
    int idx = blockIdx.x * blockDim.x + threadIdx.x;
    if (idx >= n_nodes * 80) return;
    int node = idx / 80, t = idx - node * 80;
    float nh0 = 0.f, nh1 = 0.f;
    if (t < 75) {
        const float* gir = gi + (size_t)node * GILD + 2 * t;
        const float* ghr = o1 + (size_t)node * MLD + 600 + 2 * t;
        float2 ir = *(const float2*)(gir);
        float2 iz = *(const float2*)(gir + D);
        float2 in_ = *(const float2*)(gir + 2 * D);
        float2 hr = *(const float2*)(ghr);
        float2 hz = *(const float2*)(ghr + D);
        float2 hn = *(const float2*)(ghr + 2 * D);
        float2 ho = *(const float2*)(h + (size_t)node * D + 2 * t);
        float r0 = 1.f / (1.f + expf(-(ir.x + hr.x)));
        float r1 = 1.f / (1.f + expf(-(ir.y + hr.y)));
        float z0 = 1.f / (1.f + expf(-(iz.x + hz.x)));
        float z1 = 1.f / (1.f + expf(-(iz.y + hz.y)));
        float n0 = tanhf(in_.x + r0 * hn.x);
        float n1 = tanhf(in_.y + r1 * hn.y);
        nh0 = (1.f - z0) * n0 + z0 * ho.x;
        nh1 = (1.f - z1) * n1 + z1 * ho.y;
        *(float2*)(h + (size_t)node * D + 2 * t) = make_float2(nh0, nh1);
    }
    frag_write2(Ah, Am, node, t, nh0, nh1);
}

// ---------- readout + MLP ----------
__global__ void gstart_init(int* __restrict__ gstart, int n_nodes) {
    int g = threadIdx.x;
    if (g <= NG) gstart[g] = (g == NG) ? n_nodes : 0x7fffffff;
}
__global__ void gstart_min(const int* __restrict__ gids, int* __restrict__ gstart, int n) {
    int i = blockIdx.x * blockDim.x + threadIdx.x;
    if (i < n) atomicMin(&gstart[gids[i]], i);
}
__global__ void gstart_fix(int* __restrict__ gstart) {
    if (threadIdx.x == 0)
        for (int g = NG - 1; g >= 0; --g)
            if (gstart[g] == 0x7fffffff) gstart[g] = gstart[g + 1];
}
__global__ void readout(const float* __restrict__ h, const int* __restrict__ gstart,
                        const float* __restrict__ pclass, float* __restrict__ x) {
    int g = blockIdx.x, i = threadIdx.x;
    int s = gstart[g], e = gstart[g + 1];
    if (i < D) {
        float acc = 0.f;
        for (int n = s; n < e; ++n) acc += h[(size_t)n * D + i];
        float l = logf(acc);
        if (l != l) l = 0.f;
        l = fmaxf(l, 0.f);
        x[g * XLD + i] = l;
    }
    if (i == D) x[g * XLD + D] = pclass[g];
}
__global__ void mlp_kernel(const float* __restrict__ x,
                           const float* __restrict__ fc1w, const float* __restrict__ fc1b,
                           const float* __restrict__ fc2w, const float* __restrict__ fc2b,
                           float* __restrict__ out) {
    __shared__ float xb[D + 1];
    __shared__ float hid[HIDN];
    int g = blockIdx.x, t = threadIdx.x;
    if (t < D + 1) xb[t] = x[g * XLD + t];
    __syncthreads();
    float acc = fc1b[t];
    for (int k = 0; k < D + 1; ++k) acc += xb[k] * fc1w[k * HIDN + t];
    hid[t] = acc > 0.f ? acc : 0.01f * acc;
    __syncthreads();
    if (t < 10) {
        float o = fc2b[t];
        for (int k = 0; k < HIDN; ++k) o += hid[k] * fc2w[k * 10 + t];
        out[g * 10 + t] = o;
    }
}

// ---------- launch ----------
extern "C" void kernel_launch(void* const* d_in, const int* in_sizes, int n_in,
                              void* d_out, int out_size) {
    const float* nodes  = (const float*)d_in[0];
    const float* pclass = (const float*)d_in[1];
    const int*   esrc   = (const int*)d_in[2];
    const int*   edst   = (const int*)d_in[3];
    const int*   etype  = (const int*)d_in[4];
    const int*   gids   = (const int*)d_in[5];
    const float* We     = (const float*)d_in[6];
    const float* be     = (const float*)d_in[7];
    const float* wih    = (const float*)d_in[8];
    const float* whh    = (const float*)d_in[9];
    const float* bih    = (const float*)d_in[10];
    const float* bhh    = (const float*)d_in[11];
    const float* fc1w   = (const float*)d_in[12];
    const float* fc1b   = (const float*)d_in[13];
    const float* fc2w   = (const float*)d_in[14];
    const float* fc2b   = (const float*)d_in[15];
    float* out = (float*)d_out;

    int n_nodes = in_sizes[0] / D;
    int E = in_sizes[2];

    float *h_p, *o1_p, *gi_p, *bi_p, *b1_p, *x_p;
    uint32_t *ah_p, *am_p, *ih_p, *im_p, *f1i_p, *f2i_p;
    int *degt_p, *rowptr_p, *cursor_p, *bsum_p, *ebase_p, *gstart_p;
    cudaGetSymbolAddress((void**)&h_p, g_h);
    cudaGetSymbolAddress((void**)&o1_p, g_out1);
    cudaGetSymbolAddress((void**)&gi_p, g_gi);
    cudaGetSymbolAddress((void**)&bi_p, g_biasinc);
    cudaGetSymbolAddress((void**)&ah_p, g_Ah);
    cudaGetSymbolAddress((void**)&am_p, g_Am);
    cudaGetSymbolAddress((void**)&ih_p, g_Ih);
    cudaGetSymbolAddress((void**)&im_p, g_Im);
    cudaGetSymbolAddress((void**)&f1i_p, g_F1i);
    cudaGetSymbolAddress((void**)&f2i_p, g_F2i);
    cudaGetSymbolAddress((void**)&b1_p, g_bias1);
    cudaGetSymbolAddress((void**)&x_p, g_x);
    cudaGetSymbolAddress((void**)&degt_p, g_degt);
    cudaGetSymbolAddress((void**)&rowptr_p, g_rowptr);
    cudaGetSymbolAddress((void**)&cursor_p, g_cursor);
    cudaGetSymbolAddress((void**)&bsum_p, g_bsum);
    cudaGetSymbolAddress((void**)&ebase_p, g_ebase);
    cudaGetSymbolAddress((void**)&gstart_p, g_gstart);

    int setup_items = NN * NT + (NB1 + NB2) * FBLK2 + NC1;
    setup_weights<<<(setup_items + 255) / 256, 256>>>(We, whh, wih, bhh,
        f1i_p, f2i_p, b1_p, degt_p);
    copy_h<<<(n_nodes * 80 + 255) / 256, 256>>>(nodes, h_p, ah_p, am_p, n_nodes);
    hist_kernel<<<(E + 255) / 256, 256>>>(edst, etype, degt_p, E);

    int nby = (n_nodes + 127) / 128;
    dim3 g1(NB1, nby);
    dim3 g2(NB2, nby);
    int nb = (n_nodes + 1023) / 1024;

    for (int p = 0; p < PASSES; ++p) {
        gemm_f16<<<g1, 256>>>(ah_p, am_p, f1i_p, o1_p, MLD, n_nodes, NC1, b1_p);
        if (p == 0) {
            scan_blocks<<<nb, 1024>>>(degt_p, rowptr_p, bsum_p, n_nodes);
            scan_fix<<<1, 32>>>(bsum_p, nb, rowptr_p, n_nodes);
            scan_add<<<(n_nodes + 255) / 256, 256>>>(rowptr_p, cursor_p, bsum_p, n_nodes);
            biasinc_kernel<<<(n_nodes * D + 255) / 256, 256>>>(degt_p, be, bi_p, n_nodes);
            csr_fill<<<(E + 255) / 256, 256>>>(esrc, edst, etype, cursor_p, ebase_p, E);
        }
        aggregate<<<n_nodes, 80>>>(o1_p, bi_p, rowptr_p, ebase_p, ih_p, im_p);
        gemm_f16<<<g2, 256>>>(ih_p, im_p, f2i_p, gi_p, GILD, n_nodes, 450, bih);
        gru_kernel<<<(n_nodes * 80 + 255) / 256, 256>>>(gi_p, o1_p, h_p, ah_p, am_p, n_nodes);
    }

    gstart_init<<<1, NG + 1>>>(gstart_p, n_nodes);
    gstart_min<<<(n_nodes + 255) / 256, 256>>>(gids, gstart_p, n_nodes);
    gstart_fix<<<1, 1>>>(gstart_p);
    readout<<<NG, 160>>>(h_p, gstart_p, pclass, x_p);
    mlp_kernel<<<NG, HIDN>>>(x_p, fc1w, fc1b, fc2w, fc2b, out);
}

// round 13
// speedup vs baseline: 1.4575x; 1.1378x over previous
#include <cuda_runtime.h>
#include <cuda_fp16.h>
#include <math.h>
#include <stdint.h>

#define NN 100000
#define NE 800000
#define NG 64
#define NT 4
#define D 150
#define HIDN 512
#define PASSES 5
#define NC1 1050
#define MLD 1056
#define GILD 456
#define XLD 152
#define NB1 17                     // 64-col blocks for N=1050
#define NB2 8                      // 64-col blocks for N=450
#define NBM 782
#define FBLK3 10240                // u32 per 64-col B block: 10ks x 8nt x 32lane x 4(hi0,hi1,mid0,mid1)
#define ABLK (10 * 8 * 128)        // u32 per A row block (hi or mid array)

__device__ float g_h[(size_t)NN * D];
__device__ float g_out1[(size_t)NN * MLD];
__device__ float g_gi[(size_t)NN * GILD];
__device__ float g_biasinc[(size_t)NN * D];
__device__ uint32_t g_Ah[(size_t)NBM * ABLK];
__device__ uint32_t g_Am[(size_t)NBM * ABLK];
__device__ uint32_t g_Ih[(size_t)NBM * ABLK];
__device__ uint32_t g_Im[(size_t)NBM * ABLK];
__device__ uint32_t g_F1i[NB1 * FBLK3];
__device__ uint32_t g_F2i[NB2 * FBLK3];
__device__ float g_bias1[NC1];
__device__ int   g_degt[NN * NT];
__device__ int   g_rowptr[NN + 1];
__device__ int   g_cursor[NN];
__device__ int   g_bsum[128];
__device__ int   g_ebase[NE];
__device__ int   g_gstart[NG + 1];
__device__ float g_x[NG * XLD];

__device__ __forceinline__ uint32_t packh(float x0, float x1) {
    __half2 h = __floats2half2_rn(x0, x1);
    return *reinterpret_cast<uint32_t*>(&h);
}
__device__ __forceinline__ uint32_t split2(float x0, float x1, uint32_t* mid) {
    __half h0 = __float2half_rn(x0), h1 = __float2half_rn(x1);
    float m0 = x0 - __half2float(h0), m1 = x1 - __half2float(h1);
    *mid = packh(m0, m1);
    __half2 hh = __halves2half2(h0, h1);
    return *reinterpret_cast<uint32_t*>(&hh);
}
__device__ __forceinline__ void mma_f16(float* d, const uint32_t* a, const uint32_t* b) {
    asm volatile(
        "mma.sync.aligned.m16n8k16.row.col.f32.f16.f16.f32 "
        "{%0,%1,%2,%3}, {%4,%5,%6,%7}, {%8,%9}, {%0,%1,%2,%3};"
        : "+f"(d[0]), "+f"(d[1]), "+f"(d[2]), "+f"(d[3])
        : "r"(a[0]), "r"(a[1]), "r"(a[2]), "r"(a[3]), "r"(b[0]), "r"(b[1]));
}

// word index for feature pair t (0..79) of node; matches MMA A fragment map
__device__ __forceinline__ size_t frag_widx(int node, int t) {
    int rb = node >> 7, mt = (node >> 4) & 7, r = node & 15;
    int ks = t >> 3;
    int lane = (r & 7) * 4 + (t & 3);
    int reg = (r >> 3) + 2 * ((t >> 2) & 1);
    return (((size_t)rb * 10 + ks) * 8 + mt) * 128 + lane * 4 + reg;
}
__device__ __forceinline__ void frag_write2(uint32_t* Fh, uint32_t* Fm,
                                            int node, int t, float v0, float v1) {
    uint32_t mid;
    uint32_t hi = split2(v0, v1, &mid);
    size_t wi = frag_widx(node, t);
    Fh[wi] = hi;
    Fm[wi] = mid;
}

// ---------- setup: zero degt, interleaved fragment weights (64-col blocks), bias1
__global__ void setup_weights(const float* __restrict__ We, const float* __restrict__ whh,
                              const float* __restrict__ wih, const float* __restrict__ bhh,
                              uint32_t* __restrict__ F1i, uint32_t* __restrict__ F2i,
                              float* __restrict__ bias1, int* __restrict__ degt) {
    int idx = blockIdx.x * blockDim.x + threadIdx.x;
    if (idx < NN * NT) { degt[idx] = 0; return; }
    idx -= NN * NT;
    if (idx < (NB1 + NB2) * FBLK3) {
        int two = (idx >= NB1 * FBLK3);
        int li = two ? idx - NB1 * FBLK3 : idx;
        int blk = li / FBLK3, r = li % FBLK3;
        int ks = r >> 10, r2 = r & 1023;
        int nt = r2 >> 7, r3 = r2 & 127;
        int lane = r3 >> 2, q = r3 & 3;
        int reg = q & 1;
        int hi_part = (q < 2);
        int n = blk * 64 + nt * 8 + (lane >> 2);
        int w = ks * 8 + reg * 4 + (lane & 3);
        int c0 = 2 * w, c1 = c0 + 1;
        float w0 = 0.f, w1 = 0.f;
        if (!two) {
            if (n < 600) {
                if (c0 < D) w0 = We[n * D + c0];
                if (c1 < D) w1 = We[n * D + c1];
            } else if (n < NC1) {
                if (c0 < D) w0 = whh[(n - 600) * D + c0];
                if (c1 < D) w1 = whh[(n - 600) * D + c1];
            }
        } else if (n < 450) {
            if (c0 < D) w0 = wih[n * D + c0];
            if (c1 < D) w1 = wih[n * D + c1];
        }
        uint32_t mid;
        uint32_t hi = split2(w0, w1, &mid);
        uint32_t val = hi_part ? hi : mid;
        if (!two) F1i[li] = val;
        else      F2i[li] = val;
        return;
    }
    idx -= (NB1 + NB2) * FBLK3;
    if (idx < NC1) bias1[idx] = (idx < 600) ? 0.f : bhh[idx - 600];
}

__global__ void copy_h(const float* __restrict__ nodes, float* __restrict__ h,
                       uint32_t* __restrict__ Ah, uint32_t* __restrict__ Am,
                       int n_nodes) {
    int idx = blockIdx.x * blockDim.x + threadIdx.x;
    if (idx >= n_nodes * 80) return;
    int node = idx / 80, t = idx - node * 80;
    float v0 = 0.f, v1 = 0.f;
    if (t < 75) {
        float2 v = *(const float2*)(nodes + (size_t)node * D + 2 * t);
        v0 = v.x; v1 = v.y;
        *(float2*)(h + (size_t)node * D + 2 * t) = v;
    }
    frag_write2(Ah, Am, node, t, v0, v1);
}

__global__ void hist_kernel(const int* __restrict__ dst, const int* __restrict__ etype,
                            int* __restrict__ degt, int E) {
    int e = blockIdx.x * blockDim.x + threadIdx.x;
    if (e < E) atomicAdd(&degt[dst[e] * NT + etype[e]], 1);
}

__global__ void biasinc_kernel(const int* __restrict__ degt, const float* __restrict__ be,
                               float* __restrict__ biasinc, int n_nodes) {
    int idx = blockIdx.x * blockDim.x + threadIdx.x;
    if (idx >= n_nodes * D) return;
    int node = idx / D, i = idx - node * D;
    float s = 0.f;
#pragma unroll
    for (int t = 0; t < NT; ++t) s += (float)degt[node * NT + t] * be[t * D + i];
    biasinc[idx] = s;
}

// ---------- hierarchical scan ----------
__global__ void scan_blocks(const int* __restrict__ degt, int* __restrict__ rowptr,
                            int* __restrict__ bsum, int n) {
    __shared__ int wt[32];
    int tid = threadIdx.x, lane = tid & 31, wid = tid >> 5;
    int idx = blockIdx.x * 1024 + tid;
    int v = 0;
    if (idx < n)
        v = degt[idx * NT] + degt[idx * NT + 1] + degt[idx * NT + 2] + degt[idx * NT + 3];
    int x = v;
#pragma unroll
    for (int off = 1; off < 32; off <<= 1) {
        int y = __shfl_up_sync(0xffffffffu, x, off);
        if (lane >= off) x += y;
    }
    if (lane == 31) wt[wid] = x;
    __syncthreads();
    if (wid == 0) {
        int w = wt[lane], wx = w;
#pragma unroll
        for (int off = 1; off < 32; off <<= 1) {
            int y = __shfl_up_sync(0xffffffffu, wx, off);
            if (lane >= off) wx += y;
        }
        wt[lane] = wx - w;
    }
    __syncthreads();
    int excl = wt[wid] + x - v;
    if (idx < n) rowptr[idx] = excl;
    if (tid == 1023) bsum[blockIdx.x] = excl + v;
}
__global__ void scan_fix(int* __restrict__ bsum, int nb, int* __restrict__ rowptr, int n) {
    if (threadIdx.x == 0) {
        int run = 0;
        for (int b = 0; b < nb; ++b) { int t = bsum[b]; bsum[b] = run; run += t; }
        rowptr[n] = run;
    }
}
__global__ void scan_add(int* __restrict__ rowptr, int* __restrict__ cursor,
                         const int* __restrict__ bsum, int n) {
    int idx = blockIdx.x * blockDim.x + threadIdx.x;
    if (idx >= n) return;
    int r = rowptr[idx] + bsum[idx >> 10];
    rowptr[idx] = r;
    cursor[idx] = r;
}

__global__ void csr_fill(const int* __restrict__ src, const int* __restrict__ dst,
                         const int* __restrict__ etype, int* __restrict__ cursor,
                         int* __restrict__ ebase, int E) {
    int e = blockIdx.x * blockDim.x + threadIdx.x;
    if (e >= E) return;
    int pos = atomicAdd(&cursor[dst[e]], 1);
    ebase[pos] = src[e] * MLD + etype[e] * D;
}

// ---------- fp16 3-split GEMM: CTA tile 128x64, warp grid 4Mx2N, 3 CTAs/SM ----
__global__ __launch_bounds__(256, 3) void gemm_f16(
    const uint32_t* __restrict__ Ah, const uint32_t* __restrict__ Am,
    const uint32_t* __restrict__ Fi,
    float* __restrict__ C, int ldc, int M, int N,
    const float* __restrict__ bias) {
    int tid = threadIdx.x;
    int lane = tid & 31, wid = tid >> 5;
    int wm = wid >> 1, wn = wid & 1;   // 4 x 2 warp grid
    int m0 = blockIdx.y * 128, n0 = blockIdx.x * 64;

    float acc[2][4][4];
#pragma unroll
    for (int i = 0; i < 2; ++i)
#pragma unroll
        for (int j = 0; j < 4; ++j)
#pragma unroll
            for (int r = 0; r < 4; ++r) acc[i][j][r] = 0.f;

    const uint32_t* abh = Ah + (size_t)blockIdx.y * ABLK;
    const uint32_t* abm = Am + (size_t)blockIdx.y * ABLK;
    const uint32_t* fbi = Fi + (size_t)blockIdx.x * FBLK3;

#pragma unroll
    for (int ks = 0; ks < 10; ++ks) {
        uint32_t ah[2][4], am[2][4], bh[4][2], bm[4][2];
#pragma unroll
        for (int mt = 0; mt < 2; ++mt) {
            size_t o = (((size_t)ks * 8) + wm * 2 + mt) * 128 + lane * 4;
            uint4 t = __ldg((const uint4*)(abh + o));
            ah[mt][0] = t.x; ah[mt][1] = t.y; ah[mt][2] = t.z; ah[mt][3] = t.w;
            uint4 u = __ldg((const uint4*)(abm + o));
            am[mt][0] = u.x; am[mt][1] = u.y; am[mt][2] = u.z; am[mt][3] = u.w;
        }
#pragma unroll
        for (int nt = 0; nt < 4; ++nt) {
            size_t o = (((size_t)ks * 8 + wn * 4 + nt) * 32 + lane) * 4;
            uint4 t = __ldg((const uint4*)(fbi + o));
            bh[nt][0] = t.x; bh[nt][1] = t.y;
            bm[nt][0] = t.z; bm[nt][1] = t.w;
        }
#pragma unroll
        for (int mt = 0; mt < 2; ++mt)
#pragma unroll
            for (int nt = 0; nt < 4; ++nt) {
                mma_f16(acc[mt][nt], ah[mt], bm[nt]);
                mma_f16(acc[mt][nt], am[mt], bh[nt]);
                mma_f16(acc[mt][nt], ah[mt], bh[nt]);
            }
    }

    int gi_ = lane >> 2, ti = lane & 3;
#pragma unroll
    for (int mt = 0; mt < 2; ++mt) {
#pragma unroll
        for (int nt = 0; nt < 4; ++nt) {
            int row = m0 + wm * 32 + mt * 16 + gi_;
            int col = n0 + wn * 32 + nt * 8 + 2 * ti;
            if (col >= N) continue;
            float b0 = bias[col], b1 = bias[col + 1];
            if (row < M) {
                float2 v = make_float2(acc[mt][nt][0] + b0, acc[mt][nt][1] + b1);
                *(float2*)&C[(size_t)row * ldc + col] = v;
            }
            if (row + 8 < M) {
                float2 v = make_float2(acc[mt][nt][2] + b0, acc[mt][nt][3] + b1);
                *(float2*)&C[(size_t)(row + 8) * ldc + col] = v;
            }
        }
    }
}

// ---------- CSR gather-aggregate (pair-granular), writes inc fragments ------
__global__ void aggregate(const float* __restrict__ m, const float* __restrict__ biasinc,
                          const int* __restrict__ rowptr, const int* __restrict__ ebase,
                          uint32_t* __restrict__ Ih, uint32_t* __restrict__ Im) {
    int node = blockIdx.x;
    int t = threadIdx.x;   // 0..79
    float a0 = 0.f, a1 = 0.f;
    if (t < 75) {
        float2 b = *(const float2*)(biasinc + (size_t)node * D + 2 * t);
        a0 = b.x; a1 = b.y;
        int s = rowptr[node], e = rowptr[node + 1];
        int p = s;
        for (; p + 3 < e; p += 4) {
            int b0 = ebase[p], b1 = ebase[p + 1], b2 = ebase[p + 2], b3 = ebase[p + 3];
            float2 v0 = __ldg((const float2*)(m + b0) + t);
            float2 v1 = __ldg((const float2*)(m + b1) + t);
            float2 v2 = __ldg((const float2*)(m + b2) + t);
            float2 v3 = __ldg((const float2*)(m + b3) + t);
            a0 += (v0.x + v1.x) + (v2.x + v3.x);
            a1 += (v0.y + v1.y) + (v2.y + v3.y);
        }
        for (; p < e; ++p) {
            float2 v = __ldg((const float2*)(m + ebase[p]) + t);
            a0 += v.x; a1 += v.y;
        }
    }
    frag_write2(Ih, Im, node, t, a0, a1);
}

// ---------- GRU elementwise (pair-granular) ----------
__global__ void gru_kernel(const float* __restrict__ gi, const float* __restrict__ o1,
                           float* __restrict__ h,
                           uint32_t* __restrict__ Ah, uint32_t* __restrict__ Am,
                           int n_nodes) {
    int idx = blockIdx.x * blockDim.x + threadIdx.x;
    if (idx >= n_nodes * 80) return;
    int node = idx / 80, t = idx - node * 80;
    float nh0 = 0.f, nh1 = 0.f;
    if (t < 75) {
        const float* gir = gi + (size_t)node * GILD + 2 * t;
        const float* ghr = o1 + (size_t)node * MLD + 600 + 2 * t;
        float2 ir = *(const float2*)(gir);
        float2 iz = *(const float2*)(gir + D);
        float2 in_ = *(const float2*)(gir + 2 * D);
        float2 hr = *(const float2*)(ghr);
        float2 hz = *(const float2*)(ghr + D);
        float2 hn = *(const float2*)(ghr + 2 * D);
        float2 ho = *(const float2*)(h + (size_t)node * D + 2 * t);
        float r0 = 1.f / (1.f + expf(-(ir.x + hr.x)));
        float r1 = 1.f / (1.f + expf(-(ir.y + hr.y)));
        float z0 = 1.f / (1.f + expf(-(iz.x + hz.x)));
        float z1 = 1.f / (1.f + expf(-(iz.y + hz.y)));
        float n0 = tanhf(in_.x + r0 * hn.x);
        float n1 = tanhf(in_.y + r1 * hn.y);
        nh0 = (1.f - z0) * n0 + z0 * ho.x;
        nh1 = (1.f - z1) * n1 + z1 * ho.y;
        *(float2*)(h + (size_t)node * D + 2 * t) = make_float2(nh0, nh1);
    }
    frag_write2(Ah, Am, node, t, nh0, nh1);
}

// ---------- readout + MLP ----------
__global__ void gstart_init(int* __restrict__ gstart, int n_nodes) {
    int g = threadIdx.x;
    if (g <= NG) gstart[g] = (g == NG) ? n_nodes : 0x7fffffff;
}
__global__ void gstart_min(const int* __restrict__ gids, int* __restrict__ gstart, int n) {
    int i = blockIdx.x * blockDim.x + threadIdx.x;
    if (i < n) atomicMin(&gstart[gids[i]], i);
}
__global__ void gstart_fix(int* __restrict__ gstart) {
    if (threadIdx.x == 0)
        for (int g = NG - 1; g >= 0; --g)
            if (gstart[g] == 0x7fffffff) gstart[g] = gstart[g + 1];
}
__global__ void readout(const float* __restrict__ h, const int* __restrict__ gstart,
                        const float* __restrict__ pclass, float* __restrict__ x) {
    int g = blockIdx.x, i = threadIdx.x;
    int s = gstart[g], e = gstart[g + 1];
    if (i < D) {
        float acc = 0.f;
        for (int n = s; n < e; ++n) acc += h[(size_t)n * D + i];
        float l = logf(acc);
        if (l != l) l = 0.f;
        l = fmaxf(l, 0.f);
        x[g * XLD + i] = l;
    }
    if (i == D) x[g * XLD + D] = pclass[g];
}
__global__ void mlp_kernel(const float* __restrict__ x,
                           const float* __restrict__ fc1w, const float* __restrict__ fc1b,
                           const float* __restrict__ fc2w, const float* __restrict__ fc2b,
                           float* __restrict__ out) {
    __shared__ float xb[D + 1];
    __shared__ float hid[HIDN];
    int g = blockIdx.x, t = threadIdx.x;
    if (t < D + 1) xb[t] = x[g * XLD + t];
    __syncthreads();
    float acc = fc1b[t];
    for (int k = 0; k < D + 1; ++k) acc += xb[k] * fc1w[k * HIDN + t];
    hid[t] = acc > 0.f ? acc : 0.01f * acc;
    __syncthreads();
    if (t < 10) {
        float o = fc2b[t];
        for (int k = 0; k < HIDN; ++k) o += hid[k] * fc2w[k * 10 + t];
        out[g * 10 + t] = o;
    }
}

// ---------- launch ----------
extern "C" void kernel_launch(void* const* d_in, const int* in_sizes, int n_in,
                              void* d_out, int out_size) {
    const float* nodes  = (const float*)d_in[0];
    const float* pclass = (const float*)d_in[1];
    const int*   esrc   = (const int*)d_in[2];
    const int*   edst   = (const int*)d_in[3];
    const int*   etype  = (const int*)d_in[4];
    const int*   gids   = (const int*)d_in[5];
    const float* We     = (const float*)d_in[6];
    const float* be     = (const float*)d_in[7];
    const float* wih    = (const float*)d_in[8];
    const float* whh    = (const float*)d_in[9];
    const float* bih    = (const float*)d_in[10];
    const float* bhh    = (const float*)d_in[11];
    const float* fc1w   = (const float*)d_in[12];
    const float* fc1b   = (const float*)d_in[13];
    const float* fc2w   = (const float*)d_in[14];
    const float* fc2b   = (const float*)d_in[15];
    float* out = (float*)d_out;

    int n_nodes = in_sizes[0] / D;
    int E = in_sizes[2];

    float *h_p, *o1_p, *gi_p, *bi_p, *b1_p, *x_p;
    uint32_t *ah_p, *am_p, *ih_p, *im_p, *f1i_p, *f2i_p;
    int *degt_p, *rowptr_p, *cursor_p, *bsum_p, *ebase_p, *gstart_p;
    cudaGetSymbolAddress((void**)&h_p, g_h);
    cudaGetSymbolAddress((void**)&o1_p, g_out1);
    cudaGetSymbolAddress((void**)&gi_p, g_gi);
    cudaGetSymbolAddress((void**)&bi_p, g_biasinc);
    cudaGetSymbolAddress((void**)&ah_p, g_Ah);
    cudaGetSymbolAddress((void**)&am_p, g_Am);
    cudaGetSymbolAddress((void**)&ih_p, g_Ih);
    cudaGetSymbolAddress((void**)&im_p, g_Im);
    cudaGetSymbolAddress((void**)&f1i_p, g_F1i);
    cudaGetSymbolAddress((void**)&f2i_p, g_F2i);
    cudaGetSymbolAddress((void**)&b1_p, g_bias1);
    cudaGetSymbolAddress((void**)&x_p, g_x);
    cudaGetSymbolAddress((void**)&degt_p, g_degt);
    cudaGetSymbolAddress((void**)&rowptr_p, g_rowptr);
    cudaGetSymbolAddress((void**)&cursor_p, g_cursor);
    cudaGetSymbolAddress((void**)&bsum_p, g_bsum);
    cudaGetSymbolAddress((void**)&ebase_p, g_ebase);
    cudaGetSymbolAddress((void**)&gstart_p, g_gstart);

    int setup_items = NN * NT + (NB1 + NB2) * FBLK3 + NC1;
    setup_weights<<<(setup_items + 255) / 256, 256>>>(We, whh, wih, bhh,
        f1i_p, f2i_p, b1_p, degt_p);
    copy_h<<<(n_nodes * 80 + 255) / 256, 256>>>(nodes, h_p, ah_p, am_p, n_nodes);
    hist_kernel<<<(E + 255) / 256, 256>>>(edst, etype, degt_p, E);

    int nby = (n_nodes + 127) / 128;
    dim3 g1(NB1, nby);
    dim3 g2(NB2, nby);
    int nb = (n_nodes + 1023) / 1024;

    for (int p = 0; p < PASSES; ++p) {
        gemm_f16<<<g1, 256>>>(ah_p, am_p, f1i_p, o1_p, MLD, n_nodes, NC1, b1_p);
        if (p == 0) {
            scan_blocks<<<nb, 1024>>>(degt_p, rowptr_p, bsum_p, n_nodes);
            scan_fix<<<1, 32>>>(bsum_p, nb, rowptr_p, n_nodes);
            scan_add<<<(n_nodes + 255) / 256, 256>>>(rowptr_p, cursor_p, bsum_p, n_nodes);
            biasinc_kernel<<<(n_nodes * D + 255) / 256, 256>>>(degt_p, be, bi_p, n_nodes);
            csr_fill<<<(E + 255) / 256, 256>>>(esrc, edst, etype, cursor_p, ebase_p, E);
        }
        aggregate<<<n_nodes, 80>>>(o1_p, bi_p, rowptr_p, ebase_p, ih_p, im_p);
        gemm_f16<<<g2, 256>>>(ih_p, im_p, f2i_p, gi_p, GILD, n_nodes, 450, bih);
        gru_kernel<<<(n_nodes * 80 + 255) / 256, 256>>>(gi_p, o1_p, h_p, ah_p, am_p, n_nodes);
    }

    gstart_init<<<1, NG + 1>>>(gstart_p, n_nodes);
    gstart_min<<<(n_nodes + 255) / 256, 256>>>(gids, gstart_p, n_nodes);
    gstart_fix<<<1, 1>>>(gstart_p);
    readout<<<NG, 160>>>(h_p, gstart_p, pclass, x_p);
    mlp_kernel<<<NG, HIDN>>>(x_p, fc1w, fc1b, fc2w, fc2b, out);
}